// round 17
// baseline (speedup 1.0000x reference)
#include <cuda_runtime.h>

#define BB 16
#define LL 2048
#define HH 1024
#define ZZ 512

// Scratch (device globals; no allocation allowed)
__device__ float g_k[BB * HH];          // final @ Wk
__device__ float g_kq[BB * HH];         // Wq @ k
__device__ float g_w[BB * LL];          // RAW masked logits (softmax done in k5)
__device__ float g_part[32 * BB * ZZ];  // partial column sums of latent z
__device__ float g_S2[8 * BB * ZZ];     // split-K partials of S

// Dependency counters (zero at load; reset each run inside k5_fused block 0,
// which runs strictly after every gate that reads them has passed).
__device__ unsigned g_acnt[8];          // kA blocks done per 2-batch group (16)
__device__ unsigned g_zcnt[BB];         // z-sum chunks done per batch (32)
__device__ unsigned g_fcnt[BB];         // kF slices done per batch (8)

// ---------------------------------------------------------------------------
// k12: kA + kB in ONE launch, all 384 blocks co-resident in wave 1.
//   [0,128)    kA: 16 h-chunks x 8 groups (2 batches each), unroll-32 MLP
//   [128,384)  kB: 64 row-blocks x 4 batch-groups, gated on the TWO kA groups
//              covering its batches (starts as soon as they finish).
// ---------------------------------------------------------------------------
__global__ void __launch_bounds__(512) k12_weights(
    const float* __restrict__ fin, const float* __restrict__ Wk,
    const float* __restrict__ Wq)
{
    __shared__ __align__(16) float smem[4 * HH];    // 16 KB
    const int blk = blockIdx.x;
    const int t = threadIdx.x;

    if (blk < 128) {
        // ---- kA: k[b,h] = fin[b,:] . Wk[:,h], 2 batches per block ----
        float* sfin = smem;                 // [2*HH]
        float* sred = smem + 2 * HH;        // 7 c-slices x 2 batches x 64 h
        const int bg = blk & 7;             // batches 2bg, 2bg+1
        const int hc = blk >> 3;            // 0..15, 64 h each
        for (int j = t; j < 2 * HH; j += 512)
            sfin[j] = fin[(2 * bg + (j >> 10)) * HH + (j & 1023)];
        __syncthreads();

        const int ho = t & 63;
        const int cs = t >> 6;              // 0..7, 128 c each
        const int h = hc * 64 + ho;
        float acc0 = 0.f, acc1 = 0.f;
        const float* wcol = Wk + h;
#pragma unroll 32
        for (int c = cs * 128; c < (cs + 1) * 128; ++c) {
            const float w = __ldcs(&wcol[(size_t)c * HH]);
            acc0 += w * sfin[c];
            acc1 += w * sfin[HH + c];
        }
        if (cs > 0) {
            float* d = sred + (cs - 1) * 128 + ho;
            d[0] = acc0; d[64] = acc1;
        }
        __syncthreads();
        if (cs == 0) {
#pragma unroll
            for (int s = 0; s < 7; ++s) {
                const float* d = sred + s * 128 + ho;
                acc0 += d[0]; acc1 += d[64];
            }
            g_k[(2 * bg + 0) * HH + h] = acc0;
            g_k[(2 * bg + 1) * HH + h] = acc1;
            __threadfence();
        }
        __syncthreads();
        if (t == 0) atomicAdd(&g_acnt[bg], 1u);

    } else {
        // ---- kB: kq[b,r] = Wq[r,:] . k[b,:], 4 batches per block ----
        const int e = blk - 128;
        const int rb = e >> 2;              // 0..63, 16 rows each
        const int bg = e & 3;               // batches 4bg..4bg+3
        if (t == 0) {
            while (*(volatile unsigned*)&g_acnt[2 * bg] < 16u) {}
            while (*(volatile unsigned*)&g_acnt[2 * bg + 1] < 16u) {}
            __threadfence();
        }
        __syncthreads();

        float* sk = smem;                   // 4 k-vectors, 16 KB
        for (int j = t; j < 4 * HH; j += 512)
            sk[j] = __ldcg(&g_k[(4 * bg + (j >> 10)) * HH + (j & 1023)]);
        __syncthreads();

        const int warp = t >> 5, lane = t & 31;
        const int r = rb * 16 + warp;
        const float4* wrow = (const float4*)(Wq + (size_t)r * HH);
        const float4* sk4 = (const float4*)sk;
        float acc[4] = {0.f, 0.f, 0.f, 0.f};
#pragma unroll
        for (int i = 0; i < 8; ++i) {
            const int c = lane + 32 * i;
            const float4 wv = __ldcs(&wrow[c]);
#pragma unroll
            for (int j = 0; j < 4; ++j) {
                const float4 kv = sk4[j * (HH / 4) + c];
                acc[j] += wv.x * kv.x + wv.y * kv.y + wv.z * kv.z + wv.w * kv.w;
            }
        }
#pragma unroll
        for (int j = 0; j < 4; ++j) {
            float a = acc[j];
#pragma unroll
            for (int o = 16; o; o >>= 1) a += __shfl_xor_sync(0xffffffffu, a, o);
            if (lane == 0) g_kq[(4 * bg + j) * HH + r] = a;
        }
    }
}

// ---------------------------------------------------------------------------
// k3: pure logits, 2 rows per warp. 1024 blocks x 512 threads. (at enc floor)
// ---------------------------------------------------------------------------
__global__ void __launch_bounds__(512) k3_logits(
    const float* __restrict__ enc, const int* __restrict__ mask)
{
    const int warp = threadIdx.x >> 5, lane = threadIdx.x & 31;
    const int row = (blockIdx.x * 16 + warp) * 2;
    const int b = row >> 11;
    const float4* e40 = (const float4*)(enc + (size_t)row * HH);
    const float4* e41 = (const float4*)(enc + (size_t)(row + 1) * HH);
    const float4* kq4 = (const float4*)(g_kq + b * HH);
    float acc0 = 0.f, acc1 = 0.f;
#pragma unroll
    for (int c = lane; c < HH / 4; c += 32) {
        const float4 ev0 = __ldcs(&e40[c]);
        const float4 ev1 = __ldcs(&e41[c]);
        const float4 kv = __ldg(&kq4[c]);
        acc0 += ev0.x * kv.x + ev0.y * kv.y + ev0.z * kv.z + ev0.w * kv.w;
        acc1 += ev1.x * kv.x + ev1.y * kv.y + ev1.z * kv.z + ev1.w * kv.w;
    }
#pragma unroll
    for (int o = 16; o; o >>= 1) {
        acc0 += __shfl_xor_sync(0xffffffffu, acc0, o);
        acc1 += __shfl_xor_sync(0xffffffffu, acc1, o);
    }
    if (lane == 0) {
        float v0 = acc0 * 0.03125f;
        float v1 = acc1 * 0.03125f;
        if (mask[row] == 0)     v0 = -1e9f;
        if (mask[row + 1] == 0) v1 = -1e9f;
        g_w[row]     = v0;
        g_w[row + 1] = v1;
    }
}

// ---------------------------------------------------------------------------
// k5: z-sum + kF + softmax + writers, ONE launch (proven 61.5us @70% DRAM).
// 5760 blocks x 256 threads. Block 0 resets ALL counters for next replay
// (safe: stream order puts this after every k12 gate of this replay).
// ---------------------------------------------------------------------------
__global__ void __launch_bounds__(256) k5_fused(
    const float* __restrict__ zin, const float* __restrict__ Wv,
    float* __restrict__ out)
{
    __shared__ __align__(16) float smem[640];
    __shared__ float red[8];
    __shared__ float s_max, s_inv;
    const int blk = blockIdx.x;
    const int t = threadIdx.x;

    if (blk == 0 && t == 0) {
#pragma unroll
        for (int i = 0; i < 8; ++i) g_acnt[i] = 0u;
    }

    if (blk < 512) {
        const int b = blk >> 5;
        const int chunk = blk & 31;
        const int sub = t >> 7;
        const int col4 = t & 127;
        const float4* base = (const float4*)zin
            + ((size_t)b * LL + (size_t)chunk * 64 + sub) * (ZZ / 4) + col4;
        float4 acc = make_float4(0.f, 0.f, 0.f, 0.f);
#pragma unroll
        for (int i = 0; i < 32; ++i) {
            const float4 v = __ldcs(base + (size_t)i * 2 * (ZZ / 4));
            acc.x += v.x; acc.y += v.y; acc.z += v.z; acc.w += v.w;
        }
        float4* sred = (float4*)smem;
        if (sub == 1) sred[col4] = acc;
        __syncthreads();
        if (sub == 0) {
            const float4 p = sred[col4];
            acc.x += p.x; acc.y += p.y; acc.z += p.z; acc.w += p.w;
            ((float4*)g_part)[(chunk * BB + b) * (ZZ / 4) + col4] = acc;
        }
        __threadfence();
        __syncthreads();
        if (t == 0) atomicAdd(&g_zcnt[b], 1u);

    } else if (blk < 640) {
        const int e = blk - 512;
        const int b = e >> 3;
        const int slice = e & 7;
        if (t == 0) {
            while (*(volatile unsigned*)&g_zcnt[b] < 32u) {}
            __threadfence();
        }
        __syncthreads();

        float* zs = smem;
        const int cl = t >> 2;
        const int sub = t & 3;
        const int c = 64 * slice + cl;
        float a = 0.f;
#pragma unroll
        for (int j = 0; j < 8; ++j)
            a += __ldcg(&g_part[((sub + 4 * j) * BB + b) * ZZ + c]);
#pragma unroll
        for (int o = 2; o; o >>= 1) a += __shfl_xor_sync(0xffffffffu, a, o);
        if (sub == 0) zs[cl] = a;
        __syncthreads();

#pragma unroll
        for (int h = 0; h < 2; ++h) {
            const int tt = t + 256 * h;
            float s = 0.f;
            const float* wbase = Wv + (size_t)(64 * slice) * ZZ + tt;
#pragma unroll 8
            for (int c2 = 0; c2 < 64; ++c2)
                s += zs[c2] * wbase[(size_t)c2 * ZZ];
            g_S2[(slice * BB + b) * ZZ + tt] = s;
        }
        __threadfence();
        __syncthreads();
        if (t == 0) atomicAdd(&g_fcnt[b], 1u);

    } else {
        const bool is_attn = (blk < 4736);
        const int wb = is_attn ? (blk - 640) : (blk - 4736);
        const int b = is_attn ? (wb >> 8) : (wb >> 6);

        if (!is_attn && t == 0) {
            while (*(volatile unsigned*)&g_fcnt[b] < 8u) {}
            __threadfence();
        }
        __syncthreads();

        const int warp = t >> 5, lane = t & 31;
        float lg[8];
#pragma unroll
        for (int k = 0; k < 8; ++k) lg[k] = __ldg(&g_w[b * LL + k * 256 + t]);

        float m = lg[0];
#pragma unroll
        for (int k = 1; k < 8; ++k) m = fmaxf(m, lg[k]);
#pragma unroll
        for (int o = 16; o; o >>= 1) m = fmaxf(m, __shfl_xor_sync(0xffffffffu, m, o));
        if (lane == 0) red[warp] = m;
        __syncthreads();
        if (warp == 0 && lane < 8) {
            float v = red[lane];
#pragma unroll
            for (int o = 4; o; o >>= 1) v = fmaxf(v, __shfl_xor_sync(0xffu, v, o));
            if (lane == 0) s_max = v;
        }
        __syncthreads();
        const float M = s_max;

        float s = 0.f;
#pragma unroll
        for (int k = 0; k < 8; ++k) s += __expf(lg[k] - M);
#pragma unroll
        for (int o = 16; o; o >>= 1) s += __shfl_xor_sync(0xffffffffu, s, o);
        __syncthreads();
        if (lane == 0) red[warp] = s;
        __syncthreads();
        if (warp == 0 && lane < 8) {
            float v = red[lane];
#pragma unroll
            for (int o = 4; o; o >>= 1) v += __shfl_xor_sync(0xffu, v, o);
            if (lane == 0) s_inv = 1.f / v;
        }
        __syncthreads();
        const float inv = s_inv;

        if (is_attn) {
            const long long base = (long long)b * (LL * LL / 4)
                                 + (long long)(wb & 255) * 4096;
            const int rowbase = (int)(base >> 9);
            float4* attn4 = (float4*)(out + (size_t)BB * LL * ZZ);
            float w8[8];
#pragma unroll
            for (int j = 0; j < 8; ++j)
                w8[j] = __expf(__ldg(&g_w[rowbase + j]) - M) * inv;
#pragma unroll
            for (int k = 0; k < 16; ++k) {
                const float wv = w8[k >> 1];
                __stcs(attn4 + base + k * 256 + t, make_float4(wv, wv, wv, wv));
            }
        } else {
            const long long base = (long long)b * (LL * ZZ / 4)
                                 + (long long)(wb & 63) * 4096;
            const int rowbase = (int)(base >> 7);
            const int rsub = t >> 7;
            const int col = t & 127;
            const float4* S24 = (const float4*)g_S2;
            float4 sv = make_float4(0.f, 0.f, 0.f, 0.f);
#pragma unroll
            for (int k = 0; k < 8; ++k) {
                const float4 p = __ldcg(&S24[(k * BB + b) * (ZZ / 4) + col]);
                sv.x += p.x; sv.y += p.y; sv.z += p.z; sv.w += p.w;
            }
#pragma unroll
            for (int k = 0; k < 16; ++k) {
                const float wv = __expf(__ldg(&g_w[rowbase + 2 * k + rsub]) - M) * inv;
                __stcs((float4*)out + base + k * 256 + t,
                       make_float4(wv * sv.x, wv * sv.y, wv * sv.z, wv * sv.w));
            }
        }
    }
}

// ---------------------------------------------------------------------------
extern "C" void kernel_launch(void* const* d_in, const int* in_sizes, int n_in,
                              void* d_out, int out_size)
{
    const float* enc  = (const float*)d_in[0];
    const float* fin  = (const float*)d_in[1];
    const float* zseq = (const float*)d_in[2];
    const int*   mask = (const int*)  d_in[3];
    const float* Wq   = (const float*)d_in[4];
    const float* Wk   = (const float*)d_in[5];
    const float* Wv   = (const float*)d_in[6];
    float* out = (float*)d_out;

    k12_weights<<<384, 512>>>(fin, Wk, Wq);   // kA(unroll32) + kB(per-bg gate)
    k3_logits<<<1024, 512>>>(enc, mask);      // logits (2 rows/warp)
    k5_fused<<<5760, 256>>>(zseq, Wv, out);   // z-sum + kF + softmax + writers
}